// round 3
// baseline (speedup 1.0000x reference)
#include <cuda_runtime.h>
#include <cuda_bf16.h>

// Blur_82471962018173: depthwise separable 4x4 FIR ([1,3,3,1]/4 per axis),
// input (4,128,513,513) f32, pad=1 both sides, output (4,128,512,512) f32.
//
// R3: barrier-free warp-autonomous strips. Each warp: 32 cols x 64 rows.
// Per input row: 1 lane-contiguous LDG + 3 edge loads (lanes 0-2), horizontal
// window via 6 SHFL, vertical 4-tap rolled in registers. No smem, no syncs.

#define W_IN  513
#define W_OUT 512
#define ROWS  64
#define NT    128

__global__ __launch_bounds__(NT)
void blur_kernel(const float* __restrict__ in, float* __restrict__ out) {
    const int nc   = blockIdx.z;
    const int lane = threadIdx.x & 31;
    const int warp = threadIdx.x >> 5;
    const int x0   = blockIdx.x * 128 + warp * 32;   // strip start col (0..480)
    const int y0   = blockIdx.y * ROWS;

    const float* __restrict__ inp  = in  + (size_t)nc * (W_IN  * W_IN);
    float*       __restrict__ outp = out + (size_t)nc * (W_OUT * W_OUT);

    const int  xa   = x0 - 1 + lane;                 // main load col, -1..510
    const bool a_ok = (xa >= 0);                     // xa <= 510 < 513 always
    const int  xb   = x0 + 31 + lane;                // edge cols (lanes 0..2): 511..513
    const bool b_ok = (lane < 3) && (xb < W_IN);

    const bool l29 = (lane == 29), l30 = (lane == 30), l31 = (lane == 31);

    float h[4];   // rolling horizontally-filtered rows

    auto dorow = [&](int r) -> float {
        const int yy = y0 - 1 + r;
        float a = 0.f, b = 0.f;
        if (yy >= 0 && yy < W_IN) {
            const float* rp = inp + (size_t)yy * W_IN;
            if (a_ok) a = __ldg(rp + xa);
            if (b_ok) b = __ldg(rp + xb);
        }
        float a1 = __shfl_down_sync(0xffffffffu, a, 1);
        float a2 = __shfl_down_sync(0xffffffffu, a, 2);
        float a3 = __shfl_down_sync(0xffffffffu, a, 3);
        const float b0 = __shfl_sync(0xffffffffu, b, 0);
        const float b1 = __shfl_sync(0xffffffffu, b, 1);
        const float b2 = __shfl_sync(0xffffffffu, b, 2);
        if (l31) { a1 = b0; a2 = b1; a3 = b2; }
        if (l30) { a2 = b0; a3 = b1; }
        if (l29) { a3 = b0; }
        // out col x0+lane needs in[x0+lane-1 .. x0+lane+2] = a,a1,a2,a3
        return 0.25f * (a + a3) + 0.75f * (a1 + a2);
    };

    h[0] = dorow(0);
    h[1] = dorow(1);
    h[2] = dorow(2);

    float* op = outp + (size_t)y0 * W_OUT + x0 + lane;

    #pragma unroll 4
    for (int k = 0; k < ROWS; ++k) {
        const float hn = dorow(k + 3);
        h[(k + 3) & 3] = hn;
        const float o = 0.25f * (h[k & 3] + hn)
                      + 0.75f * (h[(k + 1) & 3] + h[(k + 2) & 3]);
        op[(size_t)k * W_OUT] = o;
    }
}

extern "C" void kernel_launch(void* const* d_in, const int* in_sizes, int n_in,
                              void* d_out, int out_size) {
    const float* in = (const float*)d_in[0];   // (4,128,513,513) f32
    float* out = (float*)d_out;                // (4,128,512,512) f32
    dim3 grid(W_OUT / 128, W_OUT / ROWS, 4 * 128);  // 4 x 8 x 512
    blur_kernel<<<grid, NT>>>(in, out);
}

// round 4
// speedup vs baseline: 1.5187x; 1.5187x over previous
#include <cuda_runtime.h>
#include <cuda_bf16.h>
#include <cstdint>

// Blur_82471962018173: depthwise separable 4x4 FIR ([1,3,3,1]/4 per axis),
// input (4,128,513,513) f32, pad=1 both sides, output (4,128,512,512) f32.
//
// R4: cp.async (LDGSTS) ring pipeline. 8-slot smem row ring, DEPTH=6 rows in
// flight per block (register-free global->smem), one commit group per row,
// wait_group(5) + barrier, then hfilt via two conflict-free LDS.128 and the
// vertical 4-tap rolled in registers. Memory latency hidden by the deep pipe.

#define W_IN   513
#define W_OUT  512
#define ROWS   64
#define NT     128
#define DEPTH  6
#define SLOTS  8
#define SSTR   520   // floats per ring slot (515 used)

__device__ __forceinline__ void cp4(uint32_t dst, const void* src, int sz) {
    asm volatile("cp.async.ca.shared.global [%0], [%1], 4, %2;"
                 :: "r"(dst), "l"(src), "r"(sz));
}

__global__ __launch_bounds__(NT)
void blur_kernel(const float* __restrict__ in, float* __restrict__ out) {
    __shared__ float ring[SLOTS][SSTR];   // ring[s][i] holds input x = i-1

    const int nc = blockIdx.z;
    const int y0 = blockIdx.y * ROWS;
    const int t  = threadIdx.x;
    const int x0 = t << 2;                // output cols x0..x0+3

    const float* __restrict__ inp  = in  + (size_t)nc * (W_IN  * W_IN);
    float*       __restrict__ outp = out + (size_t)nc * (W_OUT * W_OUT);

    auto issue_row = [&](int r) {
        const int yy = y0 - 1 + r;
        const bool rowok = ((unsigned)yy < (unsigned)W_IN);
        const float* rp = inp + (size_t)yy * W_IN;
        const uint32_t sb =
            (uint32_t)__cvta_generic_to_shared(&ring[r & (SLOTS - 1)][0]);
        #pragma unroll
        for (int j = 0; j < 4; ++j) {
            const int i = t + j * NT;          // 0..511
            const int x = i - 1;               // -1..510 (only i=0 invalid)
            const bool v = rowok && (x >= 0);
            cp4(sb + i * 4, v ? (rp + x) : inp, v ? 4 : 0);
        }
        if (t < 3) {
            const int i = 512 + t;             // 512..514 -> x = 511..513
            const int x = i - 1;
            const bool v = rowok && (x < W_IN);
            cp4(sb + i * 4, v ? (rp + x) : inp, v ? 4 : 0);
        }
    };

    // prologue: fill the pipe with DEPTH rows
    #pragma unroll
    for (int j = 0; j < DEPTH; ++j) {
        issue_row(j);
        asm volatile("cp.async.commit_group;");
    }

    float4 hw[4];                              // rolling h-filtered rows
    float* op = outp + (size_t)y0 * W_OUT + x0;

    #pragma unroll 4
    for (int r = 0; r < ROWS + 3; ++r) {
        if (r + DEPTH < ROWS + 3) issue_row(r + DEPTH);
        asm volatile("cp.async.commit_group;");           // empty group on tail
        asm volatile("cp.async.wait_group %0;" :: "n"(DEPTH - 1));
        __syncthreads();                                  // row r visible to all

        const float* s = ring[r & (SLOTS - 1)];
        const float4 A = *(const float4*)(s + x0);        // x = x0-1 .. x0+2
        const float4 B = *(const float4*)(s + x0 + 4);    // x = x0+3 .. x0+6
        float4 hc;
        hc.x = 0.25f * (A.x + A.w) + 0.75f * (A.y + A.z);
        hc.y = 0.25f * (A.y + B.x) + 0.75f * (A.z + A.w);
        hc.z = 0.25f * (A.z + B.y) + 0.75f * (A.w + B.x);
        hc.w = 0.25f * (A.w + B.z) + 0.75f * (B.x + B.y);
        hw[r & 3] = hc;

        if (r >= 3) {
            const float4 a = hw[(r - 3) & 3];
            const float4 b = hw[(r - 2) & 3];
            const float4 c = hw[(r - 1) & 3];
            float4 o;
            o.x = 0.25f * (a.x + hc.x) + 0.75f * (b.x + c.x);
            o.y = 0.25f * (a.y + hc.y) + 0.75f * (b.y + c.y);
            o.z = 0.25f * (a.z + hc.z) + 0.75f * (b.z + c.z);
            o.w = 0.25f * (a.w + hc.w) + 0.75f * (b.w + c.w);
            *(float4*)(op + (size_t)(r - 3) * W_OUT) = o;
        }
    }
}

extern "C" void kernel_launch(void* const* d_in, const int* in_sizes, int n_in,
                              void* d_out, int out_size) {
    const float* in = (const float*)d_in[0];   // (4,128,513,513) f32
    float* out = (float*)d_out;                // (4,128,512,512) f32
    dim3 grid(1, W_OUT / ROWS, 4 * 128);       // 8 row-strips x 512 planes
    blur_kernel<<<grid, NT>>>(in, out);
}